// round 14
// baseline (speedup 1.0000x reference)
#include <cuda_runtime.h>
#include <math.h>

// Problem constants
#define Bc 64
#define Tc 128
#define Dc 1024
#define MU 8192            // B*T rows of xs

#define ROWS_PER_BLK 8
#define NBLK (MU / ROWS_PER_BLK)   // 1024
#define BLKS_PER_BATCH 16          // 16 blocks x 8 rows = 128 rows = one batch

// Scratch (device globals: allocation-free per harness rules)
__device__ float g_xs[MU];
__device__ float g_partial[2 * Bc];
__device__ unsigned int g_cnt[Bc];   // per-batch producer counters (reset each run)
__device__ unsigned int g_done2;     // loss-complete counter (reset each run)

// ---------------------------------------------------------------------------
// Single launch, per-batch pipelining + dead-row elision.
// The loss only reads xs[b,t] for 2 <= t < len_b (rows 0,1 and rows >= len
// are provably unused; masked candidates are -1e9 constants).  With
// len ~ U(3,128), ~50% of x is dead -> each block computes len first and
// predicates its row loads on (2 <= t < len).
// Phase 1 (1024 blocks x 256 thr): xs[b,t] = x[b,t].w_x, 8 rows/block,
//   8 predicated-independent LDG.128/thread; bump per-batch counter.
// Phase 2 (block 16b, warp 0): spin on g_cnt[b]==16, then batch b's loss:
//   loss_row(j) = log( sum_{t=j+2}^{len-1} exp(xs_t - M) ) + M - xs_{j+2}
//   (LSTM head + fc_b cancel along the softmax axis -> dead inputs.)
// Phase 3 (last of the 64): fixed-order fold of 64 partials -> out, reset.
// ---------------------------------------------------------------------------
__global__ __launch_bounds__(256) void fused_kernel(const float* __restrict__ x,
                                                    const float* __restrict__ fc_w,
                                                    const int* __restrict__ mask,
                                                    float* __restrict__ out) {
    const int tid  = threadIdx.x;
    const int lane = tid & 31;
    const int warp = tid >> 5;
    const int bid  = blockIdx.x;
    const int batch = bid >> 4;                 // 16 blocks per batch
    const bool designated = ((bid & 15) == 0);

    // ---- Phase 0: this batch's len (every warp computes it; mask row is
    //      512B, L2/L1-shared across the batch's 16 blocks) ----
    const int4 mv = ((const int4*)(mask + batch * Tc))[lane];
    int len = mv.x + mv.y + mv.z + mv.w;
#pragma unroll
    for (int off = 16; off; off >>= 1)
        len += __shfl_xor_sync(0xffffffffu, len, off);

    // ---- Phase 1: xs for this block's live rows ----
    {
        const int r0   = bid * ROWS_PER_BLK;           // global row
        const int trow = (bid & 15) * ROWS_PER_BLK;    // row within batch
        const float4* xb = (const float4*)(x + (size_t)r0 * Dc);
        const float4  w  = ((const float4*)(fc_w + 512))[tid];

        float4 a[ROWS_PER_BLK];
#pragma unroll
        for (int i = 0; i < ROWS_PER_BLK; i++) {
            const int t = trow + i;
            if (t >= 2 && t < len)
                a[i] = xb[i * 256 + tid];      // predicated, still batched MLP
            else
                a[i] = make_float4(0.f, 0.f, 0.f, 0.f);
        }

        float s[ROWS_PER_BLK];
#pragma unroll
        for (int i = 0; i < ROWS_PER_BLK; i++)
            s[i] = a[i].x * w.x + a[i].y * w.y + a[i].z * w.z + a[i].w * w.w;

#pragma unroll
        for (int off = 16; off; off >>= 1)
#pragma unroll
            for (int i = 0; i < ROWS_PER_BLK; i++)
                s[i] += __shfl_xor_sync(0xffffffffu, s[i], off);

        __shared__ float wsum[8][ROWS_PER_BLK];
        if (lane == 0) {
#pragma unroll
            for (int i = 0; i < ROWS_PER_BLK; i++) wsum[warp][i] = s[i];
        }
        __syncthreads();
        if (tid < ROWS_PER_BLK) {
            const int t = trow + tid;
            if (t >= 2 && t < len) {
                float v = 0.f;
#pragma unroll
                for (int k = 0; k < 8; k++) v += wsum[k][tid];
                g_xs[r0 + tid] = v;
            }
        }
    }

    __syncthreads();
    if (tid == 0) {
        __threadfence();                 // publish this block's g_xs slice
        atomicAdd(&g_cnt[batch], 1u);
    }

    if (!designated || warp != 0) return;   // only warp 0 of blocks 16b continue

    // ---- Phase 2: wait for THIS batch's 16 producers, then its loss ----
    {
        volatile unsigned int* cnt = &g_cnt[batch];
        while (*cnt < BLKS_PER_BATCH) __nanosleep(32);
    }
    __threadfence();                     // acquire this batch's g_xs rows
    __syncwarp();

    const int b = batch;

    // live values only; dead slots get -1e30 (never written / never needed)
    float v[4];
#pragma unroll
    for (int c = 0; c < 4; c++) {
        const int t = c * 32 + lane;
        v[c] = (t >= 2 && t < len) ? g_xs[b * Tc + t] : -1e30f;
    }

    // per-batch max over live values (constant shift for the LSE)
    float M = fmaxf(fmaxf(v[0], v[1]), fmaxf(v[2], v[3]));
#pragma unroll
    for (int off = 16; off; off >>= 1)
        M = fmaxf(M, __shfl_xor_sync(0xffffffffu, M, off));

    float e[4];
#pragma unroll
    for (int c = 0; c < 4; c++) {
        const int t = c * 32 + lane;
        e[c] = (t >= 2 && t < len) ? __expf(v[c] - M) : 0.f;
    }

    // suffix-sum scan, chunk 3 -> 0, carry = sum of later chunks
    float acc = 0.f;
    float carry = 0.f;
#pragma unroll
    for (int c = 3; c >= 0; c--) {
        float ss = e[c];
#pragma unroll
        for (int off = 1; off < 32; off <<= 1) {
            float s2 = __shfl_down_sync(0xffffffffu, ss, off);
            ss += ((lane + off) < 32) ? s2 : 0.f;
        }
        ss += carry;
        const int t = c * 32 + lane;
        if (t >= 2 && t < len)
            acc += __logf(ss) + M - v[c];
        carry = __shfl_sync(0xffffffffu, ss, 0);
    }

    // warp-reduce acc (fixed order -> deterministic)
#pragma unroll
    for (int off = 16; off; off >>= 1)
        acc += __shfl_xor_sync(0xffffffffu, acc, off);

    unsigned int done2 = 0;
    if (lane == 0) {
        int cnt = len - 2;
        if (cnt < 0) cnt = 0;
        g_partial[2 * b]     = acc;
        g_partial[2 * b + 1] = (float)cnt;
        __threadfence();
        done2 = atomicAdd(&g_done2, 1u);
    }
    done2 = __shfl_sync(0xffffffffu, done2, 0);
    if (done2 != Bc - 1) return;

    // ---- Phase 3: last loss-warp folds the 64 partials (whole warp) ----
    __threadfence();
    float tot = g_partial[2 * lane]     + g_partial[2 * (lane + 32)];
    float cnt = g_partial[2 * lane + 1] + g_partial[2 * (lane + 32) + 1];
#pragma unroll
    for (int off = 16; off; off >>= 1) {
        tot += __shfl_xor_sync(0xffffffffu, tot, off);
        cnt += __shfl_xor_sync(0xffffffffu, cnt, off);
    }
    // reset counters for next graph replay (this warp runs strictly last)
    g_cnt[lane] = 0;
    g_cnt[lane + 32] = 0;
    if (lane == 0) {
        out[0] = (cnt > 0.f) ? tot / cnt : 0.f;
        g_done2 = 0;
    }
}

// ---------------------------------------------------------------------------
extern "C" void kernel_launch(void* const* d_in, const int* in_sizes, int n_in,
                              void* d_out, int out_size) {
    const float* x    = (const float*)d_in[0];
    const int*   mask = (const int*)d_in[1];
    // d_in[2..5] (W_ih, W_hh, b_ih, b_hh) and fc_b are dead: the LSTM head
    // contribution is constant along the logsumexp axis and cancels exactly.
    const float* fc_w = (const float*)d_in[6];
    float* out = (float*)d_out;

    fused_kernel<<<NBLK, 256>>>(x, fc_w, mask, out);
}